// round 8
// baseline (speedup 1.0000x reference)
#include <cuda_runtime.h>
#include <cstdint>

#define NN    10000
#define NF    512
#define NH    32
#define NC    16
#define EMAX  360000
#define NDEC  6241                   // 79^2 upper-ish tile count (128x64 tiles)

typedef unsigned long long ull;

// ---- scratch (static device globals; no allocation allowed) ----
__device__ float g_xw1p[4 * NN * NH];  // x @ W1 partials (4 K-chunks)
__device__ float g_xw1 [NN * NH];      // sum
__device__ float g_h   [NN * NH];      // relu(A_hat @ xw1)
__device__ float g_hw2 [NN * NC];      // h @ W2
__device__ float g_z   [NN * NC];      // A_hat @ hw2
__device__ int   g_counts[NN];         // zero-initialized; k_scan re-zeros after use
__device__ int   g_rowstart[NN + 1];
__device__ int   g_cursor[NN];
__device__ ull   g_cv[EMAX];           // packed (val<<32 | col)

// ---------------------------------------------------------------
// hist: 4 edges per thread, coalesced j-strided loads, independent atomics
__global__ void k_hist(const int* __restrict__ dst, int E) {
    int base = blockIdx.x * 1024 + threadIdx.x;
#pragma unroll
    for (int j = 0; j < 4; j++) {
        int e = base + j * 256;
        if (e < E) atomicAdd(&g_counts[dst[e]], 1);
    }
}

__global__ void k_scan() {
    __shared__ int sums[1024];
    const int t = threadIdx.x;
    int loc[10];
    int s = 0;
#pragma unroll
    for (int j = 0; j < 10; j++) {
        int i = t * 10 + j;
        int c = (i < NN) ? g_counts[i] : 0;
        if (i < NN) g_counts[i] = 0;   // restore zero for next call
        loc[j] = s;
        s += c;
    }
    sums[t] = s;
    __syncthreads();
    for (int off = 1; off < 1024; off <<= 1) {
        int v = (t >= off) ? sums[t - off] : 0;
        __syncthreads();
        sums[t] += v;
        __syncthreads();
    }
    int base = (t > 0) ? sums[t - 1] : 0;
#pragma unroll
    for (int j = 0; j < 10; j++) {
        int i = t * 10 + j;
        if (i < NN) {
            int off = base + loc[j];
            g_rowstart[i] = off;
            g_cursor[i]   = off;
        }
    }
    if (t == 1023) g_rowstart[NN] = sums[1023];
}

__global__ void k_scatter(const int* __restrict__ src, const int* __restrict__ dst,
                          const float* __restrict__ w, int E) {
    int base = blockIdx.x * 1024 + threadIdx.x;
#pragma unroll
    for (int j = 0; j < 4; j++) {
        int e = base + j * 256;
        if (e < E) {
            int d = dst[e];
            int p = atomicAdd(&g_cursor[d], 1);
            ull cv = ((ull)__float_as_uint(w[e]) << 32) | (unsigned)src[e];
            g_cv[p] = cv;
        }
    }
}

// ---------------------------------------------------------------
// gemm1: partial = x[:, kb*128:(kb+1)*128] @ W1[kb*128.., :]
// BM=128, BN=32, 128 threads, 8x4 microtile, k-major x tile (LDS.128 A ops).
__global__ __launch_bounds__(128) void k_gemm1(const float* __restrict__ x,
                                               const float* __restrict__ W1) {
    __shared__ float xsT[32][132];   // k-major, padded
    __shared__ float ws [32][36];
    const int tid = threadIdx.x;
    const int tx  = tid & 7;         // 8 col-groups of 4
    const int ty  = tid >> 3;        // 16 row-groups of 8
    const int row0 = blockIdx.x * 128;
    const int kbase = blockIdx.y * 128;
    float* outbuf = g_xw1p + (size_t)blockIdx.y * (NN * NH);

    float acc[8][4] = {};

    for (int kc = 0; kc < 4; kc++) {
        int k0 = kbase + kc * 32;
        // x tile: 128 rows x 32 k = 1024 float4, 8 per thread; store transposed
#pragma unroll
        for (int jj = 0; jj < 8; jj++) {
            int f   = tid + 128 * jj;
            int r   = f >> 3;        // 0..127
            int kq  = f & 7;
            int gr  = row0 + r;
            float4 v = make_float4(0.f, 0.f, 0.f, 0.f);
            if (gr < NN) v = *(const float4*)&x[(size_t)gr * NF + k0 + kq * 4];
            xsT[kq * 4 + 0][r] = v.x;
            xsT[kq * 4 + 1][r] = v.y;
            xsT[kq * 4 + 2][r] = v.z;
            xsT[kq * 4 + 3][r] = v.w;
        }
        // W tile: 32 k x 32 cols = 256 float4, 2 per thread
#pragma unroll
        for (int jj = 0; jj < 2; jj++) {
            int f  = tid + 128 * jj;
            int r  = f >> 3;
            int kq = f & 7;
            *(float4*)&ws[r][kq * 4] = *(const float4*)&W1[(k0 + r) * NH + kq * 4];
        }
        __syncthreads();
#pragma unroll
        for (int kk = 0; kk < 32; kk++) {
            float4 a0 = *(float4*)&xsT[kk][ty * 8];
            float4 a1 = *(float4*)&xsT[kk][ty * 8 + 4];
            float4 b  = *(float4*)&ws[kk][tx * 4];
            float A[8] = {a0.x, a0.y, a0.z, a0.w, a1.x, a1.y, a1.z, a1.w};
#pragma unroll
            for (int p = 0; p < 8; p++) {
                acc[p][0] += A[p] * b.x;
                acc[p][1] += A[p] * b.y;
                acc[p][2] += A[p] * b.z;
                acc[p][3] += A[p] * b.w;
            }
        }
        __syncthreads();
    }
#pragma unroll
    for (int p = 0; p < 8; p++) {
        int gr = row0 + ty * 8 + p;
        if (gr < NN) {
            float4 o = make_float4(acc[p][0], acc[p][1], acc[p][2], acc[p][3]);
            *(float4*)&outbuf[gr * NH + tx * 4] = o;
        }
    }
}

// sum the 4 K-chunk partials
__global__ void k_add() {
    int i = blockIdx.x * blockDim.x + threadIdx.x;
    if (i < NN * NH / 4) {
        float4 a = *(float4*)&g_xw1p[0 * NN * NH + i * 4];
        float4 b = *(float4*)&g_xw1p[1 * NN * NH + i * 4];
        float4 c = *(float4*)&g_xw1p[2 * NN * NH + i * 4];
        float4 d = *(float4*)&g_xw1p[3 * NN * NH + i * 4];
        float4 o = make_float4(a.x + b.x + c.x + d.x, a.y + b.y + c.y + d.y,
                               a.z + b.z + c.z + d.z, a.w + b.w + c.w + d.w);
        *(float4*)&g_xw1[i * 4] = o;
    }
}

// ---------------------------------------------------------------
// spmm1: h = relu(A_hat @ xw1). Warp per row; uniform packed cv loads.
__global__ void k_spmm1() {
    int warp = (blockIdx.x * blockDim.x + threadIdx.x) >> 5;
    int l = threadIdx.x & 31;
    if (warp >= NN) return;
    int start = g_rowstart[warp];
    int end   = g_rowstart[warp + 1];
    float acc = 0.f;
    int e = start;
    for (; e + 3 < end; e += 4) {
        ull cv0 = g_cv[e + 0], cv1 = g_cv[e + 1], cv2 = g_cv[e + 2], cv3 = g_cv[e + 3];
        int s0 = (int)(unsigned)cv0, s1 = (int)(unsigned)cv1;
        int s2 = (int)(unsigned)cv2, s3 = (int)(unsigned)cv3;
        float w0 = __uint_as_float((unsigned)(cv0 >> 32));
        float w1 = __uint_as_float((unsigned)(cv1 >> 32));
        float w2 = __uint_as_float((unsigned)(cv2 >> 32));
        float w3 = __uint_as_float((unsigned)(cv3 >> 32));
        acc += w0 * g_xw1[s0 * NH + l];
        acc += w1 * g_xw1[s1 * NH + l];
        acc += w2 * g_xw1[s2 * NH + l];
        acc += w3 * g_xw1[s3 * NH + l];
    }
    for (; e < end; e++) {
        ull cv = g_cv[e];
        int s = (int)(unsigned)cv;
        float w = __uint_as_float((unsigned)(cv >> 32));
        acc += w * g_xw1[s * NH + l];
    }
    g_h[warp * NH + l] = fmaxf(acc, 0.f);
}

// hw2 = h @ W2 (thread per row)
__global__ void k_gemm2(const float* __restrict__ W2) {
    __shared__ float w2s[NH * NC];
    const int tid = threadIdx.x;
    for (int i = tid; i < NH * NC; i += blockDim.x) w2s[i] = W2[i];
    __syncthreads();
    int row = blockIdx.x * blockDim.x + tid;
    if (row >= NN) return;
    float acc[NC] = {};
#pragma unroll
    for (int l = 0; l < NH; l++) {
        float hv = g_h[row * NH + l];
#pragma unroll
        for (int c = 0; c < NC; c++) acc[c] += hv * w2s[l * NC + c];
    }
#pragma unroll
    for (int q = 0; q < NC; q += 4) {
        float4 o = make_float4(acc[q], acc[q + 1], acc[q + 2], acc[q + 3]);
        *(float4*)&g_hw2[row * NC + q] = o;
    }
}

// spmm2: z = A_hat @ hw2. Warp per row; half-warps process alternating edges.
__global__ void k_spmm2() {
    int warp = (blockIdx.x * blockDim.x + threadIdx.x) >> 5;
    int l = threadIdx.x & 31;
    if (warp >= NN) return;
    int f    = l & 15;
    int half = l >> 4;
    int start = g_rowstart[warp];
    int end   = g_rowstart[warp + 1];
    float acc = 0.f;
    for (int e = start + half; e < end; e += 2) {
        ull cv = g_cv[e];
        int s = (int)(unsigned)cv;
        float w = __uint_as_float((unsigned)(cv >> 32));
        acc += w * g_hw2[s * NC + f];
    }
    acc += __shfl_xor_sync(0xffffffffu, acc, 16);
    if (l < 16) g_z[warp * NC + l] = acc;
}

// ---------------------------------------------------------------
// decode: out = sigmoid(z @ z^T), SYMMETRIC. 128x64 tiles over {(i,j): j>=2i},
// count = 79^2 = 6241. Each block writes direct + transposed tile (near-diagonal
// overlap writes identical values -> benign). 256 threads, 8x4 microtile.
// zc is prescaled by 0.5 so sigmoid = fma(tanh.approx(acc), 0.5, 0.5).
__global__ __launch_bounds__(256) void k_decode(float* __restrict__ out) {
    __shared__ float zr[NC][132];
    __shared__ float zc[NC][68];
    const int t = blockIdx.x;
    // invert t -> (i, j): C(i) = i*(158-i) = 6241 - (79-i)^2
    int u = NDEC - t;                     // in (0, 6241]
    int s = (int)sqrtf((float)u);
    while (s * s < u) s++;                // s = ceil(sqrt(u))
    while (s >= 1 && (s - 1) * (s - 1) >= u) s--;
    const int i = 79 - s;
    const int j = 2 * i + (t - i * (158 - i));
    const int r0 = i * 128;
    const int c0 = j * 64;
    const int tid = threadIdx.x;

    // load 128 rows (k-major) and 64 cols (prescaled by 0.5)
#pragma unroll
    for (int jj = 0; jj < 2; jj++) {
        int f   = tid + 256 * jj;   // 0..511
        int row = f >> 2;           // 0..127
        int kq  = f & 3;
        int gr = r0 + row;
        float4 v = (gr < NN) ? *(const float4*)&g_z[gr * NC + kq * 4]
                             : make_float4(0.f, 0.f, 0.f, 0.f);
        zr[kq * 4 + 0][row] = v.x; zr[kq * 4 + 1][row] = v.y;
        zr[kq * 4 + 2][row] = v.z; zr[kq * 4 + 3][row] = v.w;
    }
    {
        int row = tid >> 2;         // 0..63
        int kq  = tid & 3;
        int gc = c0 + row;
        float4 w = (gc < NN) ? *(const float4*)&g_z[gc * NC + kq * 4]
                             : make_float4(0.f, 0.f, 0.f, 0.f);
        zc[kq * 4 + 0][row] = w.x * 0.5f;
        zc[kq * 4 + 1][row] = w.y * 0.5f;
        zc[kq * 4 + 2][row] = w.z * 0.5f;
        zc[kq * 4 + 3][row] = w.w * 0.5f;
    }
    __syncthreads();

    const int tx = tid & 15;   // 16 col groups of 4
    const int ty = tid >> 4;   // 16 row groups of 8

    float acc[8][4] = {};
#pragma unroll
    for (int k = 0; k < NC; k++) {
        float4 a0 = *(float4*)&zr[k][ty * 8];
        float4 a1 = *(float4*)&zr[k][ty * 8 + 4];
        float4 b  = *(float4*)&zc[k][tx * 4];
        float A[8] = {a0.x, a0.y, a0.z, a0.w, a1.x, a1.y, a1.z, a1.w};
#pragma unroll
        for (int p = 0; p < 8; p++) {
            acc[p][0] += A[p] * b.x;
            acc[p][1] += A[p] * b.y;
            acc[p][2] += A[p] * b.z;
            acc[p][3] += A[p] * b.w;
        }
    }

    // sigmoid: acc already = (z_r . z_c)/2, so sig = 0.5*tanh(acc) + 0.5
#pragma unroll
    for (int p = 0; p < 8; p++)
#pragma unroll
        for (int q = 0; q < 4; q++) {
            float tv;
            asm("tanh.approx.f32 %0, %1;" : "=f"(tv) : "f"(acc[p][q]));
            acc[p][q] = fmaf(tv, 0.5f, 0.5f);
        }

    // direct tile: rows r0+ty*8+p, cols c0+tx*4..
    const int gcb = c0 + tx * 4;
    if (gcb < NN) {
#pragma unroll
        for (int p = 0; p < 8; p++) {
            int gr = r0 + ty * 8 + p;
            if (gr < NN) {
                float4 o = make_float4(acc[p][0], acc[p][1], acc[p][2], acc[p][3]);
                *(float4*)&out[(size_t)gr * NN + gcb] = o;
            }
        }
    }

    // transposed tile (always; overlap writes identical values)
    {
        const int grb = r0 + ty * 8;
#pragma unroll
        for (int q = 0; q < 4; q++) {
            int gc = c0 + tx * 4 + q;
            if (gc < NN) {
                if (grb < NN) {
                    float4 o = make_float4(acc[0][q], acc[1][q], acc[2][q], acc[3][q]);
                    *(float4*)&out[(size_t)gc * NN + grb] = o;
                }
                if (grb + 4 < NN) {
                    float4 o = make_float4(acc[4][q], acc[5][q], acc[6][q], acc[7][q]);
                    *(float4*)&out[(size_t)gc * NN + grb + 4] = o;
                }
            }
        }
    }
}

// ---------------------------------------------------------------
extern "C" void kernel_launch(void* const* d_in, const int* in_sizes, int n_in,
                              void* d_out, int out_size) {
    const float* x   = (const float*)d_in[0];   // [10000, 512]
    const float* W1  = (const float*)d_in[1];   // [512, 32]
    const float* W2  = (const float*)d_in[2];   // [32, 16]
    const float* ew  = (const float*)d_in[3];   // [E]
    const int*   src = (const int*)d_in[4];     // [E]
    const int*   dst = (const int*)d_in[5];     // [E]
    float* out = (float*)d_out;
    const int E = in_sizes[3];

    const int eb4 = (E + 1023) / 1024;

    k_hist<<<eb4, 256>>>(dst, E);
    k_scan<<<1, 1024>>>();
    k_scatter<<<eb4, 256>>>(src, dst, ew, E);

    dim3 g1((NN + 127) / 128, 4);
    k_gemm1<<<g1, 128>>>(x, W1);
    k_add<<<(NN * NH / 4 + 255) / 256, 256>>>();
    k_spmm1<<<(NN * 32 + 255) / 256, 256>>>();
    k_gemm2<<<(NN + 255) / 256, 256>>>(W2);
    k_spmm2<<<(NN * 32 + 255) / 256, 256>>>();

    k_decode<<<NDEC, 256>>>(out);
}

// round 13
// speedup vs baseline: 1.1291x; 1.1291x over previous
#include <cuda_runtime.h>
#include <cstdint>

#define NN    10000
#define NF    512
#define NH    32
#define NC    16
#define EMAX  360000
#define NT64  157                    // ceil(10000/64)
#define NTRI  (NT64 * (NT64 + 1) / 2)
#define NBG1  (NT64 * 4)             // gemm1 blocks (157 row-tiles x 4 k-chunks)
#define NBADD ((NN * NH / 4 + 255) / 256)

typedef unsigned long long ull;

// ---- scratch (static device globals; no allocation allowed) ----
__device__ float g_xw1p[4 * NN * NH];  // x @ W1 partials (4 K-chunks)
__device__ float g_xw1 [NN * NH];      // sum
__device__ float g_h   [NN * NH];      // relu(A_hat @ xw1)
__device__ float g_hw2 [NN * NC];      // h @ W2
__device__ float g_z   [NN * NC];      // A_hat @ hw2
__device__ int   g_counts[NN];         // zero-initialized; k_scan re-zeros after use
__device__ int   g_rowstart[NN + 1];
__device__ int   g_cursor[NN];
__device__ ull   g_cv[EMAX];           // packed (val<<32 | col)

// sigmoid(x) = 0.5*tanh(0.5x) + 0.5
__device__ __forceinline__ float sigmoidf(float v) {
    float t;
    asm("tanh.approx.f32 %0, %1;" : "=f"(t) : "f"(v * 0.5f));
    return fmaf(t, 0.5f, 0.5f);
}

// ---------------------------------------------------------------
// kernel 1: gemm1 (blocks [0, NBG1)) fused with dst-histogram (rest).
// gemm1: partial = x[:, kb*128:(kb+1)*128] @ W1[kb*128.., :]
// BM=64, BN=32, BK=32, 256 threads, 2x4 microtile, register-prefetch pipeline.
__global__ __launch_bounds__(256) void k_gemm1_hist(const float* __restrict__ x,
                                                    const float* __restrict__ W1,
                                                    const int* __restrict__ dst, int E) {
    __shared__ float xs[64][36];
    __shared__ float ws[32][36];
    const int tid = threadIdx.x;

    if (blockIdx.x >= NBG1) {           // ---- histogram blocks ----
        int base = (blockIdx.x - NBG1) * 1024 + tid;
#pragma unroll
        for (int j = 0; j < 4; j++) {
            int e = base + j * 256;
            if (e < E) atomicAdd(&g_counts[dst[e]], 1);
        }
        return;
    }

    // ---- gemm1 blocks ----
    const int tx  = tid & 7;
    const int ty  = tid >> 3;
    const int row0 = (blockIdx.x >> 2) * 64;
    const int kb   = blockIdx.x & 3;
    const int kbase = kb * 128;
    float* outbuf = g_xw1p + (size_t)kb * (NN * NH);

    // register prefetch of tile 0
    float4 px[2], pw;
    {
        const int k0 = kbase;
#pragma unroll
        for (int j = 0; j < 2; j++) {
            int f = tid + 256 * j, r = f >> 3, kq = f & 7, gr = row0 + r;
            px[j] = make_float4(0.f, 0.f, 0.f, 0.f);
            if (gr < NN) px[j] = *(const float4*)&x[(size_t)gr * NF + k0 + kq * 4];
        }
        int r = tid >> 3, kq = tid & 7;
        pw = *(const float4*)&W1[(k0 + r) * NH + kq * 4];
    }

    float acc[2][4] = {};
    for (int kc = 0; kc < 4; kc++) {
        // store prefetched tile to smem
#pragma unroll
        for (int j = 0; j < 2; j++) {
            int f = tid + 256 * j, r = f >> 3, kq = f & 7;
            *(float4*)&xs[r][kq * 4] = px[j];
        }
        {
            int r = tid >> 3, kq = tid & 7;
            *(float4*)&ws[r][kq * 4] = pw;
        }
        __syncthreads();
        // issue next tile's loads (overlaps with compute below)
        if (kc < 3) {
            const int k0 = kbase + (kc + 1) * 32;
#pragma unroll
            for (int j = 0; j < 2; j++) {
                int f = tid + 256 * j, r = f >> 3, kq = f & 7, gr = row0 + r;
                px[j] = make_float4(0.f, 0.f, 0.f, 0.f);
                if (gr < NN) px[j] = *(const float4*)&x[(size_t)gr * NF + k0 + kq * 4];
            }
            int r = tid >> 3, kq = tid & 7;
            pw = *(const float4*)&W1[(k0 + r) * NH + kq * 4];
        }
#pragma unroll
        for (int kk = 0; kk < 32; kk++) {
            float a0 = xs[ty * 2 + 0][kk];
            float a1 = xs[ty * 2 + 1][kk];
            float4 b = *(float4*)&ws[kk][tx * 4];
            acc[0][0] += a0 * b.x; acc[0][1] += a0 * b.y;
            acc[0][2] += a0 * b.z; acc[0][3] += a0 * b.w;
            acc[1][0] += a1 * b.x; acc[1][1] += a1 * b.y;
            acc[1][2] += a1 * b.z; acc[1][3] += a1 * b.w;
        }
        __syncthreads();
    }
#pragma unroll
    for (int i = 0; i < 2; i++) {
        int gr = row0 + ty * 2 + i;
        if (gr < NN) {
            float4 o = make_float4(acc[i][0], acc[i][1], acc[i][2], acc[i][3]);
            *(float4*)&outbuf[gr * NH + tx * 4] = o;
        }
    }
}

// ---------------------------------------------------------------
__global__ void k_scan() {
    __shared__ int sums[1024];
    const int t = threadIdx.x;
    int loc[10];
    int s = 0;
#pragma unroll
    for (int j = 0; j < 10; j++) {
        int i = t * 10 + j;
        int c = (i < NN) ? g_counts[i] : 0;
        if (i < NN) g_counts[i] = 0;   // restore zero for next call
        loc[j] = s;
        s += c;
    }
    sums[t] = s;
    __syncthreads();
    for (int off = 1; off < 1024; off <<= 1) {
        int v = (t >= off) ? sums[t - off] : 0;
        __syncthreads();
        sums[t] += v;
        __syncthreads();
    }
    int base = (t > 0) ? sums[t - 1] : 0;
#pragma unroll
    for (int j = 0; j < 10; j++) {
        int i = t * 10 + j;
        if (i < NN) {
            int off = base + loc[j];
            g_rowstart[i] = off;
            g_cursor[i]   = off;
        }
    }
    if (t == 1023) g_rowstart[NN] = sums[1023];
}

// ---------------------------------------------------------------
// kernel 2: CSR scatter (blocks [0, nbS)) fused with xw1 partial-sum (rest).
__global__ __launch_bounds__(256) void k_scatter_add(const int* __restrict__ src,
                                                     const int* __restrict__ dst,
                                                     const float* __restrict__ w,
                                                     int E, int nbS) {
    const int tid = threadIdx.x;
    if (blockIdx.x < nbS) {             // ---- scatter blocks ----
        int base = blockIdx.x * 1024 + tid;
#pragma unroll
        for (int j = 0; j < 4; j++) {
            int e = base + j * 256;
            if (e < E) {
                int d = dst[e];
                int p = atomicAdd(&g_cursor[d], 1);
                ull cv = ((ull)__float_as_uint(w[e]) << 32) | (unsigned)src[e];
                g_cv[p] = cv;
            }
        }
    } else {                            // ---- add blocks ----
        int i = (blockIdx.x - nbS) * 256 + tid;
        if (i < NN * NH / 4) {
            float4 a = *(float4*)&g_xw1p[0 * NN * NH + i * 4];
            float4 b = *(float4*)&g_xw1p[1 * NN * NH + i * 4];
            float4 c = *(float4*)&g_xw1p[2 * NN * NH + i * 4];
            float4 d = *(float4*)&g_xw1p[3 * NN * NH + i * 4];
            float4 o = make_float4(a.x + b.x + c.x + d.x, a.y + b.y + c.y + d.y,
                                   a.z + b.z + c.z + d.z, a.w + b.w + c.w + d.w);
            *(float4*)&g_xw1[i * 4] = o;
        }
    }
}

// ---------------------------------------------------------------
// spmm1: h = relu(A_hat @ xw1). Warp per row; uniform packed cv loads.
__global__ void k_spmm1() {
    int warp = (blockIdx.x * blockDim.x + threadIdx.x) >> 5;
    int l = threadIdx.x & 31;
    if (warp >= NN) return;
    int start = g_rowstart[warp];
    int end   = g_rowstart[warp + 1];
    float acc = 0.f;
    int e = start;
    for (; e + 3 < end; e += 4) {
        ull cv0 = g_cv[e + 0], cv1 = g_cv[e + 1], cv2 = g_cv[e + 2], cv3 = g_cv[e + 3];
        int s0 = (int)(unsigned)cv0, s1 = (int)(unsigned)cv1;
        int s2 = (int)(unsigned)cv2, s3 = (int)(unsigned)cv3;
        float w0 = __uint_as_float((unsigned)(cv0 >> 32));
        float w1 = __uint_as_float((unsigned)(cv1 >> 32));
        float w2 = __uint_as_float((unsigned)(cv2 >> 32));
        float w3 = __uint_as_float((unsigned)(cv3 >> 32));
        acc += w0 * g_xw1[s0 * NH + l];
        acc += w1 * g_xw1[s1 * NH + l];
        acc += w2 * g_xw1[s2 * NH + l];
        acc += w3 * g_xw1[s3 * NH + l];
    }
    for (; e < end; e++) {
        ull cv = g_cv[e];
        int s = (int)(unsigned)cv;
        float w = __uint_as_float((unsigned)(cv >> 32));
        acc += w * g_xw1[s * NH + l];
    }
    g_h[warp * NH + l] = fmaxf(acc, 0.f);
}

// hw2 = h @ W2 (thread per row)
__global__ void k_gemm2(const float* __restrict__ W2) {
    __shared__ float w2s[NH * NC];
    const int tid = threadIdx.x;
    for (int i = tid; i < NH * NC; i += blockDim.x) w2s[i] = W2[i];
    __syncthreads();
    int row = blockIdx.x * blockDim.x + tid;
    if (row >= NN) return;
    float acc[NC] = {};
#pragma unroll
    for (int l = 0; l < NH; l++) {
        float hv = g_h[row * NH + l];
#pragma unroll
        for (int c = 0; c < NC; c++) acc[c] += hv * w2s[l * NC + c];
    }
#pragma unroll
    for (int q = 0; q < NC; q += 4) {
        float4 o = make_float4(acc[q], acc[q + 1], acc[q + 2], acc[q + 3]);
        *(float4*)&g_hw2[row * NC + q] = o;
    }
}

// spmm2: z = A_hat @ hw2. Warp per row; half-warps process alternating edges.
__global__ void k_spmm2() {
    int warp = (blockIdx.x * blockDim.x + threadIdx.x) >> 5;
    int l = threadIdx.x & 31;
    if (warp >= NN) return;
    int f    = l & 15;
    int half = l >> 4;
    int start = g_rowstart[warp];
    int end   = g_rowstart[warp + 1];
    float acc = 0.f;
    for (int e = start + half; e < end; e += 2) {
        ull cv = g_cv[e];
        int s = (int)(unsigned)cv;
        float w = __uint_as_float((unsigned)(cv >> 32));
        acc += w * g_hw2[s * NC + f];
    }
    acc += __shfl_xor_sync(0xffffffffu, acc, 16);
    if (l < 16) g_z[warp * NC + l] = acc;
}

// ---------------------------------------------------------------
// decode: out = sigmoid(z @ z^T), SYMMETRIC. Upper-triangle 64x64 tiles
// (12403 blocks), 4x4 microtile (proven R5 geometry), tanh-based sigmoid.
__global__ __launch_bounds__(256) void k_decode(float* __restrict__ out) {
    __shared__ float zr[NC][68];
    __shared__ float zc[NC][68];
    const int t = blockIdx.x;
    // triangular index: t = j*(j+1)/2 + i, i <= j
    int j = (int)((sqrtf(8.f * (float)t + 1.f) - 1.f) * 0.5f);
    while ((j + 1) * (j + 2) / 2 <= t) j++;
    while (j * (j + 1) / 2 > t) j--;
    const int i = t - j * (j + 1) / 2;
    const int r0 = i * 64;
    const int c0 = j * 64;
    const int tid = threadIdx.x;

    {
        int row = tid >> 2;   // 0..63
        int kq  = tid & 3;
        int gr = r0 + row;
        float4 v = (gr < NN) ? *(const float4*)&g_z[gr * NC + kq * 4]
                             : make_float4(0.f, 0.f, 0.f, 0.f);
        zr[kq * 4 + 0][row] = v.x; zr[kq * 4 + 1][row] = v.y;
        zr[kq * 4 + 2][row] = v.z; zr[kq * 4 + 3][row] = v.w;
        int gc = c0 + row;
        float4 w = (gc < NN) ? *(const float4*)&g_z[gc * NC + kq * 4]
                             : make_float4(0.f, 0.f, 0.f, 0.f);
        zc[kq * 4 + 0][row] = w.x; zc[kq * 4 + 1][row] = w.y;
        zc[kq * 4 + 2][row] = w.z; zc[kq * 4 + 3][row] = w.w;
    }
    __syncthreads();

    const int tx = tid & 15;
    const int ty = tid >> 4;

    float acc[4][4] = {};
#pragma unroll
    for (int k = 0; k < NC; k++) {
        float4 a = *(float4*)&zr[k][ty * 4];
        float4 b = *(float4*)&zc[k][tx * 4];
        acc[0][0] += a.x * b.x; acc[0][1] += a.x * b.y; acc[0][2] += a.x * b.z; acc[0][3] += a.x * b.w;
        acc[1][0] += a.y * b.x; acc[1][1] += a.y * b.y; acc[1][2] += a.y * b.z; acc[1][3] += a.y * b.w;
        acc[2][0] += a.z * b.x; acc[2][1] += a.z * b.y; acc[2][2] += a.z * b.z; acc[2][3] += a.z * b.w;
        acc[3][0] += a.w * b.x; acc[3][1] += a.w * b.y; acc[3][2] += a.w * b.z; acc[3][3] += a.w * b.w;
    }

    float s[4][4];
#pragma unroll
    for (int p = 0; p < 4; p++)
#pragma unroll
        for (int q = 0; q < 4; q++) s[p][q] = sigmoidf(acc[p][q]);

    const int gcb = c0 + tx * 4;
    if (gcb < NN) {
#pragma unroll
        for (int p = 0; p < 4; p++) {
            int gr = r0 + ty * 4 + p;
            if (gr < NN) {
                float4 o = make_float4(s[p][0], s[p][1], s[p][2], s[p][3]);
                *(float4*)&out[(size_t)gr * NN + gcb] = o;
            }
        }
    }

    if (i != j) {
        const int grb = r0 + ty * 4;
        if (grb < NN) {
#pragma unroll
            for (int q = 0; q < 4; q++) {
                int gc = c0 + tx * 4 + q;
                if (gc < NN) {
                    float4 o = make_float4(s[0][q], s[1][q], s[2][q], s[3][q]);
                    *(float4*)&out[(size_t)gc * NN + grb] = o;
                }
            }
        }
    }
}

// ---------------------------------------------------------------
extern "C" void kernel_launch(void* const* d_in, const int* in_sizes, int n_in,
                              void* d_out, int out_size) {
    const float* x   = (const float*)d_in[0];   // [10000, 512]
    const float* W1  = (const float*)d_in[1];   // [512, 32]
    const float* W2  = (const float*)d_in[2];   // [32, 16]
    const float* ew  = (const float*)d_in[3];   // [E]
    const int*   src = (const int*)d_in[4];     // [E]
    const int*   dst = (const int*)d_in[5];     // [E]
    float* out = (float*)d_out;
    const int E = in_sizes[3];

    const int nbS = (E + 1023) / 1024;

    k_gemm1_hist<<<NBG1 + nbS, 256>>>(x, W1, dst, E);     // gemm1 || hist
    k_scan<<<1, 1024>>>();
    k_scatter_add<<<nbS + NBADD, 256>>>(src, dst, ew, E, nbS);  // scatter || add
    k_spmm1<<<(NN * 32 + 255) / 256, 256>>>();
    k_gemm2<<<(NN + 255) / 256, 256>>>(W2);
    k_spmm2<<<(NN * 32 + 255) / 256, 256>>>();

    k_decode<<<NTRI, 256>>>(out);
}